// round 2
// baseline (speedup 1.0000x reference)
#include <cuda_runtime.h>
#include <cuda_bf16.h>
#include <math.h>

// Problem constants
#define BATCH   4
#define SEQ_N   2048
#define SEQ_J   2048
#define DIM     768
#define HEADS   12
#define DHEAD   64
#define INNER   (HEADS * DHEAD)   // 768
#define SCALE   0.125f             // 64^-0.5

#define ROWS_TOTAL (BATCH * SEQ_N) // 8192

// ---------------------------------------------------------------------------
// Scratch (static device allocations; no cudaMalloc allowed)
// ---------------------------------------------------------------------------
__device__ float g_xn[(size_t)ROWS_TOTAL * DIM];     // layernorm(x)        24 MB
__device__ float g_q [(size_t)ROWS_TOTAL * INNER];   // q (natural layout)  24 MB
__device__ float g_kv[(size_t)ROWS_TOTAL * 128];     // [k|v] per context    4 MB
__device__ float g_ao[(size_t)ROWS_TOTAL * INNER];   // attn output         24 MB

// ---------------------------------------------------------------------------
// LayerNorm: one block per row of 768
// ---------------------------------------------------------------------------
__global__ void ln_kernel(const float* __restrict__ x,
                          const float* __restrict__ w,
                          float* __restrict__ y)
{
    const int row = blockIdx.x;
    const float* xr = x + (size_t)row * DIM;
    float v[3];
    float s = 0.f, s2 = 0.f;
#pragma unroll
    for (int t = 0; t < 3; t++) {
        int i = threadIdx.x + t * 256;
        float vv = xr[i];
        v[t] = vv;
        s += vv; s2 += vv * vv;
    }
    // warp reduce
#pragma unroll
    for (int o = 16; o > 0; o >>= 1) {
        s  += __shfl_xor_sync(0xffffffffu, s,  o);
        s2 += __shfl_xor_sync(0xffffffffu, s2, o);
    }
    __shared__ float rs[8], rs2[8];
    int wid = threadIdx.x >> 5, lid = threadIdx.x & 31;
    if (lid == 0) { rs[wid] = s; rs2[wid] = s2; }
    __syncthreads();
    if (wid == 0) {
        s  = (lid < 8) ? rs[lid]  : 0.f;
        s2 = (lid < 8) ? rs2[lid] : 0.f;
#pragma unroll
        for (int o = 4; o > 0; o >>= 1) {
            s  += __shfl_xor_sync(0xffffffffu, s,  o);
            s2 += __shfl_xor_sync(0xffffffffu, s2, o);
        }
        if (lid == 0) { rs[0] = s; rs2[0] = s2; }
    }
    __syncthreads();
    const float mu   = rs[0] * (1.f / DIM);
    const float var  = rs2[0] * (1.f / DIM) - mu * mu;
    const float rstd = rsqrtf(var + 1e-5f);
    float* yr = y + (size_t)row * DIM;
#pragma unroll
    for (int t = 0; t < 3; t++) {
        int i = threadIdx.x + t * 256;
        yr[i] = (v[t] - mu) * rstd * w[i];
    }
}

// ---------------------------------------------------------------------------
// SGEMM: C[M,N] = alpha * A[M,K] @ B[K,N]    (row-major, fp32)
// BM=128, BN=64, BK=16, 256 threads, 8x4 microtile.
// Requires M%128==0, N%64==0, K%16==0 (true for all three calls).
// ---------------------------------------------------------------------------
__global__ __launch_bounds__(256)
void sgemm_kernel(const float* __restrict__ A, const float* __restrict__ B,
                  float* __restrict__ C, int M, int N, int K, float alpha)
{
    __shared__ float As[16][128];
    __shared__ float Bs[16][64];

    const int tid = threadIdx.x;
    const int m0 = blockIdx.y * 128;
    const int n0 = blockIdx.x * 64;
    const int tr = tid >> 4;        // 0..15  (row group, 8 rows each)
    const int tc = tid & 15;        // 0..15  (col group, 4 cols each)

    float acc[8][4];
#pragma unroll
    for (int i = 0; i < 8; i++)
#pragma unroll
        for (int j = 0; j < 4; j++) acc[i][j] = 0.f;

    for (int k0 = 0; k0 < K; k0 += 16) {
        // load A tile (128x16) transposed into As[16][128]
#pragma unroll
        for (int t = 0; t < 2; t++) {
            int e  = tid + t * 256;          // 0..511 float4 slots
            int m  = e >> 2;
            int kq = (e & 3) * 4;
            float4 a4 = *reinterpret_cast<const float4*>(
                &A[(size_t)(m0 + m) * K + k0 + kq]);
            As[kq + 0][m] = a4.x;
            As[kq + 1][m] = a4.y;
            As[kq + 2][m] = a4.z;
            As[kq + 3][m] = a4.w;
        }
        // load B tile (16x64)
        {
            int r = tid >> 4;
            int c = (tid & 15) * 4;
            *reinterpret_cast<float4*>(&Bs[r][c]) =
                *reinterpret_cast<const float4*>(&B[(size_t)(k0 + r) * N + n0 + c]);
        }
        __syncthreads();
#pragma unroll
        for (int kk = 0; kk < 16; kk++) {
            float a[8], bb[4];
#pragma unroll
            for (int i = 0; i < 8; i++) a[i] = As[kk][tr * 8 + i];
#pragma unroll
            for (int j = 0; j < 4; j++) bb[j] = Bs[kk][tc * 4 + j];
#pragma unroll
            for (int i = 0; i < 8; i++)
#pragma unroll
                for (int j = 0; j < 4; j++) acc[i][j] += a[i] * bb[j];
        }
        __syncthreads();
    }

#pragma unroll
    for (int i = 0; i < 8; i++) {
        float4 r;
        r.x = acc[i][0] * alpha;
        r.y = acc[i][1] * alpha;
        r.z = acc[i][2] * alpha;
        r.w = acc[i][3] * alpha;
        *reinterpret_cast<float4*>(
            &C[(size_t)(m0 + tr * 8 + i) * N + n0 + tc * 4]) = r;
    }
}

// ---------------------------------------------------------------------------
// Flash attention (fp32). One thread owns one q-row; K/V tiles in smem.
// q layout: [b, n, h, d] (natural from GEMM). kv layout: [b*j, 128] (k|v).
// Output: [b, n, h*d].
// Grid: (SEQ_N/128, HEADS, BATCH), 128 threads.
// ---------------------------------------------------------------------------
#define TJ 64
__global__ __launch_bounds__(128)
void attn_kernel(const float* __restrict__ q, const float* __restrict__ kv,
                 const float* __restrict__ mask, float* __restrict__ o)
{
    __shared__ float4 Ks[TJ][16];
    __shared__ float4 Vs[TJ][16];

    const int row_l = threadIdx.x;
    const int row   = blockIdx.x * 128 + row_l;
    const int h     = blockIdx.y;
    const int b     = blockIdx.z;

    // load q row (scaled) into registers
    float4 qv[16];
    {
        const float4* qr = reinterpret_cast<const float4*>(
            &q[((size_t)(b * SEQ_N) + row) * INNER + h * DHEAD]);
#pragma unroll
        for (int dv = 0; dv < 16; dv++) {
            float4 t = qr[dv];
            t.x *= SCALE; t.y *= SCALE; t.z *= SCALE; t.w *= SCALE;
            qv[dv] = t;
        }
    }

    float4 acc[16];
#pragma unroll
    for (int dv = 0; dv < 16; dv++) acc[dv] = make_float4(0.f, 0.f, 0.f, 0.f);
    float m = -INFINITY, l = 0.f;

    const size_t bj_base = (size_t)b * SEQ_J;
    const float* mrow_base = &mask[((size_t)(b * SEQ_N) + row) * SEQ_J];

    for (int jt = 0; jt < SEQ_J; jt += TJ) {
        __syncthreads();
        // cooperative load of K,V tiles (64 rows x 64 floats each)
#pragma unroll
        for (int t = 0; t < 8; t++) {
            int e  = threadIdx.x + t * 128;   // 0..1023
            int jj = e >> 4;
            int dv = e & 15;
            const float4* src = reinterpret_cast<const float4*>(
                &kv[(bj_base + jt + jj) * 128]);
            Ks[jj][dv] = src[dv];
            Vs[jj][dv] = src[16 + dv];
        }
        __syncthreads();

        const float* mrow = mrow_base + jt;
#pragma unroll 2
        for (int jj = 0; jj < TJ; jj++) {
            float s = 0.f;
#pragma unroll
            for (int dv = 0; dv < 16; dv++) {
                float4 k4 = Ks[jj][dv];
                float4 q4 = qv[dv];
                s += q4.x * k4.x + q4.y * k4.y + q4.z * k4.z + q4.w * k4.w;
            }
            s += mrow[jj];

            if (s > m) {                      // rare after warmup
                float corr = __expf(m - s);   // exp(-inf)=0 on first hit
                m = s;
                l *= corr;
#pragma unroll
                for (int dv = 0; dv < 16; dv++) {
                    acc[dv].x *= corr; acc[dv].y *= corr;
                    acc[dv].z *= corr; acc[dv].w *= corr;
                }
            }
            float p = __expf(s - m);
            l += p;
#pragma unroll
            for (int dv = 0; dv < 16; dv++) {
                float4 v4 = Vs[jj][dv];
                acc[dv].x += p * v4.x; acc[dv].y += p * v4.y;
                acc[dv].z += p * v4.z; acc[dv].w += p * v4.w;
            }
        }
    }

    const float inv = 1.f / l;
    float4* orow = reinterpret_cast<float4*>(
        &o[((size_t)(b * SEQ_N) + row) * INNER + h * DHEAD]);
#pragma unroll
    for (int dv = 0; dv < 16; dv++) {
        float4 r = acc[dv];
        r.x *= inv; r.y *= inv; r.z *= inv; r.w *= inv;
        orow[dv] = r;
    }
}

// ---------------------------------------------------------------------------
// Launch
// ---------------------------------------------------------------------------
extern "C" void kernel_launch(void* const* d_in, const int* in_sizes, int n_in,
                              void* d_out, int out_size)
{
    const float* x       = (const float*)d_in[0];
    const float* context = (const float*)d_in[1];
    const float* mask    = (const float*)d_in[2];
    const float* ln_w    = (const float*)d_in[3];
    const float* Wq      = (const float*)d_in[4];
    const float* Wkv     = (const float*)d_in[5];
    const float* Wo      = (const float*)d_in[6];
    float* out = (float*)d_out;

    float *xn, *q, *kvb, *ao;
    cudaGetSymbolAddress((void**)&xn,  g_xn);
    cudaGetSymbolAddress((void**)&q,   g_q);
    cudaGetSymbolAddress((void**)&kvb, g_kv);
    cudaGetSymbolAddress((void**)&ao,  g_ao);

    // 1. layernorm
    ln_kernel<<<ROWS_TOTAL, 256>>>(x, ln_w, xn);

    // 2. q = ln(x) @ Wq   (scale folded into epilogue is NOT applied here;
    //    attention applies SCALE at q load — pass alpha=1)
    sgemm_kernel<<<dim3(INNER / 64, ROWS_TOTAL / 128), 256>>>(
        xn, Wq, q, ROWS_TOTAL, INNER, DIM, 1.0f);

    // 3. kv = context @ Wkv  ([8192, 128], k = cols 0..63, v = 64..127)
    sgemm_kernel<<<dim3(128 / 64, ROWS_TOTAL / 128), 256>>>(
        context, Wkv, kvb, ROWS_TOTAL, 128, DIM, 1.0f);

    // 4. attention
    attn_kernel<<<dim3(SEQ_N / 128, HEADS, BATCH), 128>>>(q, kvb, mask, ao);

    // 5. out = ao @ Wo
    sgemm_kernel<<<dim3(DIM / 64, ROWS_TOTAL / 128), 256>>>(
        ao, Wo, out, ROWS_TOTAL, DIM, INNER, 1.0f);
}

// round 3
// speedup vs baseline: 1.6317x; 1.6317x over previous
#include <cuda_runtime.h>
#include <cuda_bf16.h>
#include <math.h>

// Problem constants
#define BATCH   4
#define SEQ_N   2048
#define SEQ_J   2048
#define DIM     768
#define HEADS   12
#define DHEAD   64
#define INNER   (HEADS * DHEAD)   // 768
#define SCALE   0.125f             // 64^-0.5

#define ROWS_TOTAL (BATCH * SEQ_N) // 8192

// ---------------------------------------------------------------------------
// Scratch (static device allocations; no cudaMalloc allowed)
// ---------------------------------------------------------------------------
__device__ float g_xn[(size_t)ROWS_TOTAL * DIM];     // layernorm(x)        24 MB
__device__ float g_q [(size_t)ROWS_TOTAL * INNER];   // q (natural layout)  24 MB
__device__ float g_kv[(size_t)ROWS_TOTAL * 128];     // [k|v] per context    4 MB
__device__ float g_ao[(size_t)ROWS_TOTAL * INNER];   // attn output         24 MB

// ---------------------------------------------------------------------------
// LayerNorm: one block per row of 768
// ---------------------------------------------------------------------------
__global__ void ln_kernel(const float* __restrict__ x,
                          const float* __restrict__ w,
                          float* __restrict__ y)
{
    const int row = blockIdx.x;
    const float* xr = x + (size_t)row * DIM;
    float v[3];
    float s = 0.f, s2 = 0.f;
#pragma unroll
    for (int t = 0; t < 3; t++) {
        int i = threadIdx.x + t * 256;
        float vv = xr[i];
        v[t] = vv;
        s += vv; s2 += vv * vv;
    }
    // warp reduce
#pragma unroll
    for (int o = 16; o > 0; o >>= 1) {
        s  += __shfl_xor_sync(0xffffffffu, s,  o);
        s2 += __shfl_xor_sync(0xffffffffu, s2, o);
    }
    __shared__ float rs[8], rs2[8];
    int wid = threadIdx.x >> 5, lid = threadIdx.x & 31;
    if (lid == 0) { rs[wid] = s; rs2[wid] = s2; }
    __syncthreads();
    if (wid == 0) {
        s  = (lid < 8) ? rs[lid]  : 0.f;
        s2 = (lid < 8) ? rs2[lid] : 0.f;
#pragma unroll
        for (int o = 4; o > 0; o >>= 1) {
            s  += __shfl_xor_sync(0xffffffffu, s,  o);
            s2 += __shfl_xor_sync(0xffffffffu, s2, o);
        }
        if (lid == 0) { rs[0] = s; rs2[0] = s2; }
    }
    __syncthreads();
    const float mu   = rs[0] * (1.f / DIM);
    const float var  = rs2[0] * (1.f / DIM) - mu * mu;
    const float rstd = rsqrtf(var + 1e-5f);
    float* yr = y + (size_t)row * DIM;
#pragma unroll
    for (int t = 0; t < 3; t++) {
        int i = threadIdx.x + t * 256;
        yr[i] = (v[t] - mu) * rstd * w[i];
    }
}

// ---------------------------------------------------------------------------
// SGEMM: C[M,N] = alpha * A[M,K] @ B[K,N]    (row-major, fp32)
// BM=128, BN=64, BK=16, 256 threads, 8x4 microtile.
// Requires M%128==0, N%64==0, K%16==0 (true for all three calls).
// ---------------------------------------------------------------------------
__global__ __launch_bounds__(256)
void sgemm_kernel(const float* __restrict__ A, const float* __restrict__ B,
                  float* __restrict__ C, int M, int N, int K, float alpha)
{
    __shared__ float As[16][128];
    __shared__ float Bs[16][64];

    const int tid = threadIdx.x;
    const int m0 = blockIdx.y * 128;
    const int n0 = blockIdx.x * 64;
    const int tr = tid >> 4;        // 0..15  (row group, 8 rows each)
    const int tc = tid & 15;        // 0..15  (col group, 4 cols each)

    float acc[8][4];
#pragma unroll
    for (int i = 0; i < 8; i++)
#pragma unroll
        for (int j = 0; j < 4; j++) acc[i][j] = 0.f;

    for (int k0 = 0; k0 < K; k0 += 16) {
        // load A tile (128x16) transposed into As[16][128]
#pragma unroll
        for (int t = 0; t < 2; t++) {
            int e  = tid + t * 256;          // 0..511 float4 slots
            int m  = e >> 2;
            int kq = (e & 3) * 4;
            float4 a4 = *reinterpret_cast<const float4*>(
                &A[(size_t)(m0 + m) * K + k0 + kq]);
            As[kq + 0][m] = a4.x;
            As[kq + 1][m] = a4.y;
            As[kq + 2][m] = a4.z;
            As[kq + 3][m] = a4.w;
        }
        // load B tile (16x64)
        {
            int r = tid >> 4;
            int c = (tid & 15) * 4;
            *reinterpret_cast<float4*>(&Bs[r][c]) =
                *reinterpret_cast<const float4*>(&B[(size_t)(k0 + r) * N + n0 + c]);
        }
        __syncthreads();
#pragma unroll
        for (int kk = 0; kk < 16; kk++) {
            float a[8], bb[4];
#pragma unroll
            for (int i = 0; i < 8; i++) a[i] = As[kk][tr * 8 + i];
#pragma unroll
            for (int j = 0; j < 4; j++) bb[j] = Bs[kk][tc * 4 + j];
#pragma unroll
            for (int i = 0; i < 8; i++)
#pragma unroll
                for (int j = 0; j < 4; j++) acc[i][j] += a[i] * bb[j];
        }
        __syncthreads();
    }

#pragma unroll
    for (int i = 0; i < 8; i++) {
        float4 r;
        r.x = acc[i][0] * alpha;
        r.y = acc[i][1] * alpha;
        r.z = acc[i][2] * alpha;
        r.w = acc[i][3] * alpha;
        *reinterpret_cast<float4*>(
            &C[(size_t)(m0 + tr * 8 + i) * N + n0 + tc * 4]) = r;
    }
}

// ---------------------------------------------------------------------------
// Flash attention (fp32). One thread owns one q-row; K/V tiles in smem.
// q layout: [b, n, h, d] (natural from GEMM). kv layout: [b*j, 128] (k|v).
// Output: [b, n, h*d].
// Grid: (SEQ_N/128, HEADS, BATCH), 128 threads.
// ---------------------------------------------------------------------------
#define TJ 64
__global__ __launch_bounds__(128)
void attn_kernel(const float* __restrict__ q, const float* __restrict__ kv,
                 const float* __restrict__ mask, float* __restrict__ o)
{
    __shared__ float4 Ks[TJ][16];
    __shared__ float4 Vs[TJ][16];

    const int row_l = threadIdx.x;
    const int row   = blockIdx.x * 128 + row_l;
    const int h     = blockIdx.y;
    const int b     = blockIdx.z;

    // load q row (scaled) into registers
    float4 qv[16];
    {
        const float4* qr = reinterpret_cast<const float4*>(
            &q[((size_t)(b * SEQ_N) + row) * INNER + h * DHEAD]);
#pragma unroll
        for (int dv = 0; dv < 16; dv++) {
            float4 t = qr[dv];
            t.x *= SCALE; t.y *= SCALE; t.z *= SCALE; t.w *= SCALE;
            qv[dv] = t;
        }
    }

    float4 acc[16];
#pragma unroll
    for (int dv = 0; dv < 16; dv++) acc[dv] = make_float4(0.f, 0.f, 0.f, 0.f);
    float m = -INFINITY, l = 0.f;

    const size_t bj_base = (size_t)b * SEQ_J;
    const float* mrow_base = &mask[((size_t)(b * SEQ_N) + row) * SEQ_J];

    for (int jt = 0; jt < SEQ_J; jt += TJ) {
        __syncthreads();
        // cooperative load of K,V tiles (64 rows x 64 floats each)
#pragma unroll
        for (int t = 0; t < 8; t++) {
            int e  = threadIdx.x + t * 128;   // 0..1023
            int jj = e >> 4;
            int dv = e & 15;
            const float4* src = reinterpret_cast<const float4*>(
                &kv[(bj_base + jt + jj) * 128]);
            Ks[jj][dv] = src[dv];
            Vs[jj][dv] = src[16 + dv];
        }
        __syncthreads();

        const float* mrow = mrow_base + jt;
#pragma unroll 2
        for (int jj = 0; jj < TJ; jj++) {
            float s = 0.f;
#pragma unroll
            for (int dv = 0; dv < 16; dv++) {
                float4 k4 = Ks[jj][dv];
                float4 q4 = qv[dv];
                s += q4.x * k4.x + q4.y * k4.y + q4.z * k4.z + q4.w * k4.w;
            }
            s += mrow[jj];

            if (s > m) {                      // rare after warmup
                float corr = __expf(m - s);   // exp(-inf)=0 on first hit
                m = s;
                l *= corr;
#pragma unroll
                for (int dv = 0; dv < 16; dv++) {
                    acc[dv].x *= corr; acc[dv].y *= corr;
                    acc[dv].z *= corr; acc[dv].w *= corr;
                }
            }
            float p = __expf(s - m);
            l += p;
#pragma unroll
            for (int dv = 0; dv < 16; dv++) {
                float4 v4 = Vs[jj][dv];
                acc[dv].x += p * v4.x; acc[dv].y += p * v4.y;
                acc[dv].z += p * v4.z; acc[dv].w += p * v4.w;
            }
        }
    }

    const float inv = 1.f / l;
    float4* orow = reinterpret_cast<float4*>(
        &o[((size_t)(b * SEQ_N) + row) * INNER + h * DHEAD]);
#pragma unroll
    for (int dv = 0; dv < 16; dv++) {
        float4 r = acc[dv];
        r.x *= inv; r.y *= inv; r.z *= inv; r.w *= inv;
        orow[dv] = r;
    }
}

// ---------------------------------------------------------------------------
// Launch
// ---------------------------------------------------------------------------
extern "C" void kernel_launch(void* const* d_in, const int* in_sizes, int n_in,
                              void* d_out, int out_size)
{
    const float* x       = (const float*)d_in[0];
    const float* context = (const float*)d_in[1];
    const float* mask    = (const float*)d_in[2];
    const float* ln_w    = (const float*)d_in[3];
    const float* Wq      = (const float*)d_in[4];
    const float* Wkv     = (const float*)d_in[5];
    const float* Wo      = (const float*)d_in[6];
    float* out = (float*)d_out;

    float *xn, *q, *kvb, *ao;
    cudaGetSymbolAddress((void**)&xn,  g_xn);
    cudaGetSymbolAddress((void**)&q,   g_q);
    cudaGetSymbolAddress((void**)&kvb, g_kv);
    cudaGetSymbolAddress((void**)&ao,  g_ao);

    // 1. layernorm
    ln_kernel<<<ROWS_TOTAL, 256>>>(x, ln_w, xn);

    // 2. q = ln(x) @ Wq   (scale folded into epilogue is NOT applied here;
    //    attention applies SCALE at q load — pass alpha=1)
    sgemm_kernel<<<dim3(INNER / 64, ROWS_TOTAL / 128), 256>>>(
        xn, Wq, q, ROWS_TOTAL, INNER, DIM, 1.0f);

    // 3. kv = context @ Wkv  ([8192, 128], k = cols 0..63, v = 64..127)
    sgemm_kernel<<<dim3(128 / 64, ROWS_TOTAL / 128), 256>>>(
        context, Wkv, kvb, ROWS_TOTAL, 128, DIM, 1.0f);

    // 4. attention
    attn_kernel<<<dim3(SEQ_N / 128, HEADS, BATCH), 128>>>(q, kvb, mask, ao);

    // 5. out = ao @ Wo
    sgemm_kernel<<<dim3(DIM / 64, ROWS_TOTAL / 128), 256>>>(
        ao, Wo, out, ROWS_TOTAL, DIM, INNER, 1.0f);
}